// round 7
// baseline (speedup 1.0000x reference)
#include <cuda_runtime.h>
#include <mma.h>
#include <cstdint>

using namespace nvcuda;

// Problem constants
#define B_  4
#define L_  2048
#define E_  512
#define H_  8
#define D_  64
#define M_  (B_*L_)
#define MASK_ELEMS ((size_t)B_*L_*L_)

// ---------------------------------------------------------------------------
// Scratch (device globals; no allocations allowed)
// ---------------------------------------------------------------------------
__device__ float g_QH[B_*H_*L_*D_];   // [(b*H+h)][l][d]
__device__ float g_KH[B_*H_*L_*D_];
__device__ float g_VH[B_*H_*L_*D_];
__device__ float g_CTX[(size_t)M_*E_]; // [b*L+l][h*D+d]
__device__ float g_FC [(size_t)M_*E_];
__device__ unsigned char g_mask[MASK_ELEMS];
__device__ unsigned int  g_flagA, g_flagB;

__device__ __forceinline__ float tf32r(float f) {
    uint32_t r; asm("cvt.rna.tf32.f32 %0, %1;" : "=r"(r) : "f"(f));
    return __uint_as_float(r);
}

// ---------------------------------------------------------------------------
// Mask dtype probe + canonicalize (proven in R2)
// ---------------------------------------------------------------------------
__global__ void probe_init() { g_flagA = 0u; g_flagB = 0u; }

__global__ __launch_bounds__(256) void probe_mask(const unsigned int* __restrict__ mw)
{
    size_t i = (size_t)blockIdx.x * blockDim.x + threadIdx.x;
    unsigned int w = mw[i];
    unsigned int a = (w != 0u && w != 1u) ? 1u : 0u;
    unsigned int b = (w != 0u && w != 0x3F800000u) ? 1u : 0u;
    for (int o = 16; o > 0; o >>= 1) {
        a |= __shfl_xor_sync(0xffffffffu, a, o);
        b |= __shfl_xor_sync(0xffffffffu, b, o);
    }
    if ((threadIdx.x & 31) == 0) {
        if (a) atomicOr(&g_flagA, 1u);
        if (b) atomicOr(&g_flagB, 1u);
    }
}

__global__ __launch_bounds__(256) void convert_mask(const void* __restrict__ mraw)
{
    size_t i = (size_t)blockIdx.x * blockDim.x + threadIdx.x;
    unsigned char v;
    if (!g_flagA)       v = (unsigned char)(((const int*)mraw)[i] != 0);
    else if (!g_flagB)  v = (unsigned char)(((const float*)mraw)[i] != 0.f);
    else                v = (unsigned char)(((const unsigned char*)mraw)[i] != 0);
    g_mask[i] = v;
}

// ---------------------------------------------------------------------------
// Projection GEMM: 128x128 tile, 8x8 micro-kernel, 256 threads (fp32 SIMT).
// ---------------------------------------------------------------------------
template<int LAYOUT>
__global__ __launch_bounds__(256) void gemm_bias(
    const float* __restrict__ Xin, const float* __restrict__ W,
    const float* __restrict__ bias, int dst_sel)
{
    const float* X = Xin ? Xin : (const float*)g_CTX;
    float* out = (dst_sel == 0) ? g_QH : (dst_sel == 1) ? g_KH
               : (dst_sel == 2) ? g_VH : g_FC;

    __shared__ float As[16][132];
    __shared__ float Bs[16][132];

    const int tid = threadIdx.x;
    const int tx = tid & 15, ty = tid >> 4;
    const int m0 = blockIdx.x * 128, n0 = blockIdx.y * 128;

    float acc[8][8] = {};

    for (int k0 = 0; k0 < E_; k0 += 16) {
        #pragma unroll
        for (int it = 0; it < 2; it++) {
            int idx = tid + it * 256;
            int row = idx >> 2, kk = (idx & 3) * 4;
            float4 a = *(const float4*)(X + (size_t)(m0 + row) * E_ + k0 + kk);
            float4 w = *(const float4*)(W + (size_t)(n0 + row) * E_ + k0 + kk);
            As[kk+0][row] = a.x; As[kk+1][row] = a.y; As[kk+2][row] = a.z; As[kk+3][row] = a.w;
            Bs[kk+0][row] = w.x; Bs[kk+1][row] = w.y; Bs[kk+2][row] = w.z; Bs[kk+3][row] = w.w;
        }
        __syncthreads();
        #pragma unroll
        for (int kk = 0; kk < 16; kk++) {
            float4 a0 = *(const float4*)&As[kk][ty*4];
            float4 a1 = *(const float4*)&As[kk][ty*4 + 64];
            float4 b0 = *(const float4*)&Bs[kk][tx*4];
            float4 b1 = *(const float4*)&Bs[kk][tx*4 + 64];
            float av[8] = {a0.x,a0.y,a0.z,a0.w, a1.x,a1.y,a1.z,a1.w};
            float bv[8] = {b0.x,b0.y,b0.z,b0.w, b1.x,b1.y,b1.z,b1.w};
            #pragma unroll
            for (int i = 0; i < 8; i++)
                #pragma unroll
                for (int j = 0; j < 8; j++)
                    acc[i][j] += av[i] * bv[j];
        }
        __syncthreads();
    }

    float4 bb0 = *(const float4*)(bias + n0 + tx*4);
    float4 bb1 = *(const float4*)(bias + n0 + 64 + tx*4);
    #pragma unroll
    for (int i = 0; i < 8; i++) {
        int m = m0 + ((i < 4) ? (ty*4 + i) : (64 + ty*4 + i - 4));
        float4 r0 = make_float4(acc[i][0]+bb0.x, acc[i][1]+bb0.y, acc[i][2]+bb0.z, acc[i][3]+bb0.w);
        float4 r1 = make_float4(acc[i][4]+bb1.x, acc[i][5]+bb1.y, acc[i][6]+bb1.z, acc[i][7]+bb1.w);
        if (LAYOUT == 0) {
            *(float4*)(out + (size_t)m * E_ + n0 + tx*4)      = r0;
            *(float4*)(out + (size_t)m * E_ + n0 + 64 + tx*4) = r1;
        } else {
            int b = m >> 11, l = m & (L_-1);
            int c0 = n0 + tx*4, c1 = n0 + 64 + tx*4;
            *(float4*)(out + (((size_t)(b*H_ + (c0>>6)) * L_) + l) * D_ + (c0 & 63)) = r0;
            *(float4*)(out + (((size_t)(b*H_ + (c1>>6)) * L_) + l) * D_ + (c1 & 63)) = r1;
        }
    }
}

// ---------------------------------------------------------------------------
// Attention via WMMA tf32, single pass over K. Coalesced per-row exp/store.
// Block: 256 thr (8 warps), 128 q-rows, 16 k-tiles of 128.
// ---------------------------------------------------------------------------
#define LDQ 72
#define LDSS 136
#define SM_Q  0
#define SM_K  (128*LDQ)
#define SM_V  (2*128*LDQ)
#define SM_S  (3*128*LDQ)
#define ATTN_DSMEM ((3*128*LDQ + 128*LDSS) * 4)   // 180224 bytes

typedef wmma::fragment<wmma::matrix_a, 16, 16, 8, wmma::precision::tf32, wmma::row_major> FragA;
typedef wmma::fragment<wmma::matrix_b, 16, 16, 8, wmma::precision::tf32, wmma::col_major> FragBc;
typedef wmma::fragment<wmma::matrix_b, 16, 16, 8, wmma::precision::tf32, wmma::row_major> FragBr;
typedef wmma::fragment<wmma::accumulator, 16, 16, 8, float> FragC;

extern __shared__ float sm_attn[];

__global__ __launch_bounds__(256, 1) void attn_wmma(float* __restrict__ attn)
{
    const int tid = threadIdx.x;
    const int w = tid >> 5, lane = tid & 31;
    const int bh = blockIdx.y, b = bh >> 3, h = bh & 7;
    const int q0 = blockIdx.x * 128;

    // wmma warp tiles: S-phase rows 32*wm / cols 64*wn ; PV rows 32*wm / d-cols 32*wn
    const int wm = w & 3, wn = w >> 2;

    float* Qs = sm_attn + SM_Q;
    float* Ks = sm_attn + SM_K;
    float* Vs = sm_attn + SM_V;
    float* Ss = sm_attn + SM_S;
    __shared__ float s_inv[128];

    const float* Qb = g_QH + (size_t)bh * (L_*D_) + (size_t)q0 * D_;
    const float* Kb = g_KH + (size_t)bh * (L_*D_);
    const float* Vb = g_VH + (size_t)bh * (L_*D_);

    // coalesced row-ownership: warp w owns rows 16w .. 16w+15
    const int row0 = 16 * w;
    float* attn_base = attn + ((size_t)(h*B_ + b) * L_ + q0) * L_;
    const unsigned char* mask_base = g_mask + ((size_t)b * L_ + q0) * L_;

    // Fill Q (tf32-rounded), batched loads
    {
        float4 t[2];
        #pragma unroll
        for (int it = 0; it < 2; it++) {
            int idx = tid + it*256;
            t[it] = *(const float4*)(Qb + (size_t)(idx >> 4) * D_ + (idx & 15) * 4);
        }
        #pragma unroll
        for (int it = 0; it < 2; it++) {
            int idx = tid + it*256;
            int row = idx >> 4, c4 = (idx & 15) * 4;
            *(float4*)&Qs[row*LDQ + c4] =
                make_float4(tf32r(t[it].x), tf32r(t[it].y), tf32r(t[it].z), tf32r(t[it].w));
        }
        // remaining 3/4 of Q
        #pragma unroll
        for (int it = 2; it < 8; it++) {
            int idx = tid + it*256;
            float4 f = *(const float4*)(Qb + (size_t)(idx >> 4) * D_ + (idx & 15) * 4);
            int row = idx >> 4, c4 = (idx & 15) * 4;
            *(float4*)&Qs[row*LDQ + c4] = make_float4(tf32r(f.x), tf32r(f.y), tf32r(f.z), tf32r(f.w));
        }
    }
    __syncthreads();

    FragC cf[2][2];
    #pragma unroll
    for (int i = 0; i < 2; i++)
        #pragma unroll
        for (int j = 0; j < 2; j++)
            wmma::fill_fragment(cf[i][j], 0.f);

    float rsum[16];
    #pragma unroll
    for (int i = 0; i < 16; i++) rsum[i] = 0.f;

    for (int kt = 0; kt < 16; kt++) {
        // ---- Fill K and V tiles (loads batched, then stores) ----
        const float* Kt = Kb + (size_t)kt * 128 * D_;
        const float* Vt = Vb + (size_t)kt * 128 * D_;
        {
            float4 kr[4], vr[4];
            #pragma unroll
            for (int it = 0; it < 4; it++) {
                int idx = tid + it*256;
                kr[it] = *(const float4*)(Kt + (size_t)(idx >> 4) * D_ + (idx & 15) * 4);
                vr[it] = *(const float4*)(Vt + (size_t)(idx >> 4) * D_ + (idx & 15) * 4);
            }
            #pragma unroll
            for (int it = 0; it < 4; it++) {
                int idx = tid + it*256;
                int row = idx >> 4, c4 = (idx & 15) * 4;
                *(float4*)&Ks[row*LDQ + c4] = make_float4(tf32r(kr[it].x), tf32r(kr[it].y), tf32r(kr[it].z), tf32r(kr[it].w));
                *(float4*)&Vs[row*LDQ + c4] = make_float4(tf32r(vr[it].x), tf32r(vr[it].y), tf32r(vr[it].z), tf32r(vr[it].w));
            }
            float4 kr2[4], vr2[4];
            #pragma unroll
            for (int it = 0; it < 4; it++) {
                int idx = tid + (it+4)*256;
                kr2[it] = *(const float4*)(Kt + (size_t)(idx >> 4) * D_ + (idx & 15) * 4);
                vr2[it] = *(const float4*)(Vt + (size_t)(idx >> 4) * D_ + (idx & 15) * 4);
            }
            #pragma unroll
            for (int it = 0; it < 4; it++) {
                int idx = tid + (it+4)*256;
                int row = idx >> 4, c4 = (idx & 15) * 4;
                *(float4*)&Ks[row*LDQ + c4] = make_float4(tf32r(kr2[it].x), tf32r(kr2[it].y), tf32r(kr2[it].z), tf32r(kr2[it].w));
                *(float4*)&Vs[row*LDQ + c4] = make_float4(tf32r(vr2[it].x), tf32r(vr2[it].y), tf32r(vr2[it].z), tf32r(vr2[it].w));
            }
        }
        __syncthreads();

        // ---- S = Q K^T (warp: 32 rows x 64 cols); accum frags, A loaded per k ----
        {
            FragC c[2][4];
            #pragma unroll
            for (int i = 0; i < 2; i++)
                #pragma unroll
                for (int n = 0; n < 4; n++)
                    wmma::fill_fragment(c[i][n], 0.f);
            #pragma unroll
            for (int k = 0; k < 8; k++) {
                FragA a0, a1;
                wmma::load_matrix_sync(a0, &Qs[(32*wm)      * LDQ + k*8], LDQ);
                wmma::load_matrix_sync(a1, &Qs[(32*wm + 16) * LDQ + k*8], LDQ);
                #pragma unroll
                for (int n = 0; n < 4; n++) {
                    FragBc bf;
                    wmma::load_matrix_sync(bf, &Ks[(64*wn + 16*n) * LDQ + k*8], LDQ);
                    wmma::mma_sync(c[0][n], a0, bf, c[0][n]);
                    wmma::mma_sync(c[1][n], a1, bf, c[1][n]);
                }
            }
            #pragma unroll
            for (int n = 0; n < 4; n++) {
                wmma::store_matrix_sync(&Ss[(32*wm)      * LDSS + 64*wn + 16*n], c[0][n], LDSS, wmma::mem_row_major);
                wmma::store_matrix_sync(&Ss[(32*wm + 16) * LDSS + 64*wn + 16*n], c[1][n], LDSS, wmma::mem_row_major);
            }
        }
        __syncthreads();

        // ---- exp + mask, coalesced per row: lane covers 4 cols of 128 ----
        {
            #pragma unroll
            for (int i = 0; i < 16; i++) {
                int r = row0 + i;
                float* sp = &Ss[r * LDSS + 4*lane];
                float4 s4 = *(float4*)sp;
                uchar4 m = *(const uchar4*)(mask_base + (size_t)r * L_ + kt*128 + 4*lane);
                float4 e;
                e.x = m.x ? 0.f : exp2f(s4.x * 0.18033688f);
                e.y = m.y ? 0.f : exp2f(s4.y * 0.18033688f);
                e.z = m.z ? 0.f : exp2f(s4.z * 0.18033688f);
                e.w = m.w ? 0.f : exp2f(s4.w * 0.18033688f);
                rsum[i] += (e.x + e.y) + (e.z + e.w);
                *(float4*)(attn_base + (size_t)r * L_ + kt*128 + 4*lane) = e;
                *(float4*)sp = make_float4(tf32r(e.x), tf32r(e.y), tf32r(e.z), tf32r(e.w));
            }
        }
        __syncthreads();

        // ---- ctx += P @ V (warp: 32 rows x 32 d-cols) ----
        #pragma unroll
        for (int k = 0; k < 16; k++) {
            FragA pa0, pa1;
            FragBr vb0, vb1;
            wmma::load_matrix_sync(pa0, &Ss[(32*wm)      * LDSS + 8*k], LDSS);
            wmma::load_matrix_sync(pa1, &Ss[(32*wm + 16) * LDSS + 8*k], LDSS);
            wmma::load_matrix_sync(vb0, &Vs[(8*k) * LDQ + 32*wn],      LDQ);
            wmma::load_matrix_sync(vb1, &Vs[(8*k) * LDQ + 32*wn + 16], LDQ);
            wmma::mma_sync(cf[0][0], pa0, vb0, cf[0][0]);
            wmma::mma_sync(cf[0][1], pa0, vb1, cf[0][1]);
            wmma::mma_sync(cf[1][0], pa1, vb0, cf[1][0]);
            wmma::mma_sync(cf[1][1], pa1, vb1, cf[1][1]);
        }
        __syncthreads();
    }

    // ---- row sums -> inverse (warp-exclusive rows, shfl reduce) ----
    #pragma unroll
    for (int i = 0; i < 16; i++) {
        float t = rsum[i];
        #pragma unroll
        for (int o = 16; o > 0; o >>= 1) t += __shfl_xor_sync(0xffffffffu, t, o);
        if (lane == 0) s_inv[row0 + i] = 1.f / t;
    }

    // ---- ctx to smem, then normalized coalesced store ----
    #pragma unroll
    for (int i = 0; i < 2; i++)
        #pragma unroll
        for (int j = 0; j < 2; j++)
            wmma::store_matrix_sync(&Ss[(32*wm + 16*i) * LDSS + 32*wn + 16*j], cf[i][j], LDSS, wmma::mem_row_major);
    __syncthreads();

    #pragma unroll
    for (int i = 0; i < 16; i++) {
        int r = row0 + i;
        float inv = s_inv[r];
        float2 f = *(float2*)&Ss[r * LDSS + 2*lane];
        *(float2*)(g_CTX + ((size_t)b * L_ + q0 + r) * E_ + h*D_ + 2*lane) =
            make_float2(f.x * inv, f.y * inv);
    }

    // ---- rescale this block's attn stripe (coalesced rows) ----
    #pragma unroll
    for (int i = 0; i < 16; i++) {
        int r = row0 + i;
        float inv = s_inv[r];
        float* ap = attn_base + (size_t)r * L_;
        #pragma unroll 4
        for (int c = 4*lane; c < L_; c += 128) {
            float4 e = *(float4*)(ap + c);
            *(float4*)(ap + c) = make_float4(e.x*inv, e.y*inv, e.z*inv, e.w*inv);
        }
    }
}

// ---------------------------------------------------------------------------
// Fused residual + LayerNorm over rows of 512.
// ---------------------------------------------------------------------------
__global__ __launch_bounds__(256) void ln_kernel(
    const float* __restrict__ resid, const float* __restrict__ gamma,
    const float* __restrict__ beta, float* __restrict__ out)
{
    const int row = blockIdx.x;
    const int t = threadIdx.x;
    const float* fc = g_FC + (size_t)row * E_;
    const float* rsd = resid + (size_t)row * E_;

    float x0 = fc[t]       + rsd[t];
    float x1 = fc[t + 256] + rsd[t + 256];
    float s = x0 + x1, sq = x0*x0 + x1*x1;
    #pragma unroll
    for (int o = 16; o > 0; o >>= 1) {
        s  += __shfl_xor_sync(0xffffffffu, s,  o);
        sq += __shfl_xor_sync(0xffffffffu, sq, o);
    }
    __shared__ float ws[8], wq[8];
    __shared__ float s_mu, s_rstd;
    if ((t & 31) == 0) { ws[t >> 5] = s; wq[t >> 5] = sq; }
    __syncthreads();
    if (t == 0) {
        float S = 0.f, Q = 0.f;
        #pragma unroll
        for (int i = 0; i < 8; i++) { S += ws[i]; Q += wq[i]; }
        float mu = S * (1.f / E_);
        float var = Q * (1.f / E_) - mu * mu;
        s_mu = mu; s_rstd = rsqrtf(var + 1e-5f);
    }
    __syncthreads();
    float mu = s_mu, rstd = s_rstd;
    out[(size_t)row * E_ + t]       = (x0 - mu) * rstd * gamma[t]       + beta[t];
    out[(size_t)row * E_ + t + 256] = (x1 - mu) * rstd * gamma[t + 256] + beta[t + 256];
}

// ---------------------------------------------------------------------------
extern "C" void kernel_launch(void* const* d_in, const int* in_sizes, int n_in,
                              void* d_out, int out_size)
{
    const float* q    = (const float*)d_in[0];
    const float* k    = (const float*)d_in[1];
    const float* v    = (const float*)d_in[2];
    const void*  mask = d_in[3];
    const float* Wq   = (const float*)d_in[4];
    const float* bq   = (const float*)d_in[5];
    const float* Wk   = (const float*)d_in[6];
    const float* bk   = (const float*)d_in[7];
    const float* Wv   = (const float*)d_in[8];
    const float* bv   = (const float*)d_in[9];
    const float* Wfc  = (const float*)d_in[10];
    const float* bfc  = (const float*)d_in[11];
    const float* gamma= (const float*)d_in[12];
    const float* beta = (const float*)d_in[13];

    float* out  = (float*)d_out;
    float* attn = out + (size_t)M_ * E_;

    cudaFuncSetAttribute(attn_wmma, cudaFuncAttributeMaxDynamicSharedMemorySize, ATTN_DSMEM);

    probe_init<<<1, 1>>>();
    probe_mask<<<(MASK_ELEMS/4)/256, 256>>>((const unsigned int*)mask);
    convert_mask<<<MASK_ELEMS/256, 256>>>(mask);

    dim3 gproj(M_/128, E_/128);                  // (64, 4)
    gemm_bias<1><<<gproj, 256>>>(q, Wq, bq, 0);
    gemm_bias<1><<<gproj, 256>>>(k, Wk, bk, 1);
    gemm_bias<1><<<gproj, 256>>>(v, Wv, bv, 2);

    dim3 gattn(L_/128, B_*H_);                   // (16, 32)
    attn_wmma<<<gattn, 256, ATTN_DSMEM>>>(attn);

    gemm_bias<0><<<gproj, 256>>>(nullptr, Wfc, bfc, 3);

    ln_kernel<<<M_, 256>>>(q, gamma, beta, out);
}

// round 13
// speedup vs baseline: 1.8921x; 1.8921x over previous
#include <cuda_runtime.h>
#include <cuda_fp16.h>
#include <cstdint>

// Problem constants
#define B_  4
#define L_  2048
#define E_  512
#define H_  8
#define D_  64
#define M_  (B_*L_)
#define MASK_ELEMS ((size_t)B_*L_*L_)
#define LDH 72               // halves per smem row (16B-aligned stride 144B)
#define EC  0.18033688f      // log2(e)/8

// ---------------------------------------------------------------------------
// Scratch (device globals; no allocations allowed)
// ---------------------------------------------------------------------------
__device__ float g_QH[B_*H_*L_*D_];     // [(b*H+h)][l][d]
__device__ float g_KH[B_*H_*L_*D_];
__device__ float g_VH[B_*H_*L_*D_];
__device__ float g_CTX[(size_t)M_*E_];  // [b*L+l][h*D+d]
__device__ float g_FC [(size_t)M_*E_];
__device__ __half g_maskh[MASK_ELEMS];  // 1.0 = keep, 0.0 = masked
__device__ unsigned int g_flagA = 0, g_flagB = 0;   // static-init; monotone OR

// ---------------------------------------------------------------------------
// PTX helpers
// ---------------------------------------------------------------------------
__device__ __forceinline__ uint32_t smem_u32(const void* p) {
    uint32_t a;
    asm("{ .reg .u64 t; cvta.to.shared.u64 t, %1; cvt.u32.u64 %0, t; }" : "=r"(a) : "l"(p));
    return a;
}
__device__ __forceinline__ uint32_t h2_u32(__half2 h) {
    union { __half2 h; uint32_t u; } cv; cv.h = h; return cv.u;
}
__device__ __forceinline__ void ldsm_x4(uint32_t& r0, uint32_t& r1, uint32_t& r2, uint32_t& r3, uint32_t a) {
    asm volatile("ldmatrix.sync.aligned.m8n8.x4.shared.b16 {%0,%1,%2,%3}, [%4];"
        : "=r"(r0), "=r"(r1), "=r"(r2), "=r"(r3) : "r"(a));
}
__device__ __forceinline__ void ldsm_x4t(uint32_t& r0, uint32_t& r1, uint32_t& r2, uint32_t& r3, uint32_t a) {
    asm volatile("ldmatrix.sync.aligned.m8n8.x4.trans.shared.b16 {%0,%1,%2,%3}, [%4];"
        : "=r"(r0), "=r"(r1), "=r"(r2), "=r"(r3) : "r"(a));
}
__device__ __forceinline__ void mma_f16(float* c, const uint32_t* a, uint32_t b0, uint32_t b1) {
    asm volatile("mma.sync.aligned.m16n8k16.row.col.f32.f16.f16.f32 "
        "{%0,%1,%2,%3}, {%4,%5,%6,%7}, {%8,%9}, {%0,%1,%2,%3};"
        : "+f"(c[0]), "+f"(c[1]), "+f"(c[2]), "+f"(c[3])
        : "r"(a[0]), "r"(a[1]), "r"(a[2]), "r"(a[3]), "r"(b0), "r"(b1));
}

// ---------------------------------------------------------------------------
// Mask dtype probe (flags static-init; monotone OR -> deterministic) + fp16
// canonicalize (multiplier form: masked -> 0, keep -> 1).
// ---------------------------------------------------------------------------
__global__ __launch_bounds__(256) void probe_mask(const unsigned int* __restrict__ mw)
{
    size_t i = (size_t)blockIdx.x * blockDim.x + threadIdx.x;   // < 4M words (16.7MB, safe)
    unsigned int w = mw[i];
    unsigned int a = (w != 0u && w != 1u) ? 1u : 0u;
    unsigned int b = (w != 0u && w != 0x3F800000u) ? 1u : 0u;
    for (int o = 16; o > 0; o >>= 1) {
        a |= __shfl_xor_sync(0xffffffffu, a, o);
        b |= __shfl_xor_sync(0xffffffffu, b, o);
    }
    if ((threadIdx.x & 31) == 0) {
        if (a) atomicOr(&g_flagA, 1u);
        if (b) atomicOr(&g_flagB, 1u);
    }
}

__global__ __launch_bounds__(256) void convert_mask(const void* __restrict__ mraw)
{
    size_t i = (size_t)blockIdx.x * blockDim.x + threadIdx.x;
    unsigned char v;
    if (!g_flagA)       v = (unsigned char)(((const int*)mraw)[i] != 0);
    else if (!g_flagB)  v = (unsigned char)(((const float*)mraw)[i] != 0.f);
    else                v = (unsigned char)(((const unsigned char*)mraw)[i] != 0);
    g_maskh[i] = __float2half(v ? 0.f : 1.f);   // multiplier: masked -> 0
}

// ---------------------------------------------------------------------------
// Projection GEMM: 128x128 tile, 8x8 micro-kernel, 256 threads (fp32 SIMT).
// ---------------------------------------------------------------------------
template<int LAYOUT>
__global__ __launch_bounds__(256) void gemm_bias(
    const float* __restrict__ Xin, const float* __restrict__ W,
    const float* __restrict__ bias, int dst_sel)
{
    const float* X = Xin ? Xin : (const float*)g_CTX;
    float* out = (dst_sel == 0) ? g_QH : (dst_sel == 1) ? g_KH
               : (dst_sel == 2) ? g_VH : g_FC;

    __shared__ float As[16][132];
    __shared__ float Bs[16][132];

    const int tid = threadIdx.x;
    const int tx = tid & 15, ty = tid >> 4;
    const int m0 = blockIdx.x * 128, n0 = blockIdx.y * 128;

    float acc[8][8] = {};

    for (int k0 = 0; k0 < E_; k0 += 16) {
        #pragma unroll
        for (int it = 0; it < 2; it++) {
            int idx = tid + it * 256;
            int row = idx >> 2, kk = (idx & 3) * 4;
            float4 a = *(const float4*)(X + (size_t)(m0 + row) * E_ + k0 + kk);
            float4 w = *(const float4*)(W + (size_t)(n0 + row) * E_ + k0 + kk);
            As[kk+0][row] = a.x; As[kk+1][row] = a.y; As[kk+2][row] = a.z; As[kk+3][row] = a.w;
            Bs[kk+0][row] = w.x; Bs[kk+1][row] = w.y; Bs[kk+2][row] = w.z; Bs[kk+3][row] = w.w;
        }
        __syncthreads();
        #pragma unroll
        for (int kk = 0; kk < 16; kk++) {
            float4 a0 = *(const float4*)&As[kk][ty*4];
            float4 a1 = *(const float4*)&As[kk][ty*4 + 64];
            float4 b0 = *(const float4*)&Bs[kk][tx*4];
            float4 b1 = *(const float4*)&Bs[kk][tx*4 + 64];
            float av[8] = {a0.x,a0.y,a0.z,a0.w, a1.x,a1.y,a1.z,a1.w};
            float bv[8] = {b0.x,b0.y,b0.z,b0.w, b1.x,b1.y,b1.z,b1.w};
            #pragma unroll
            for (int i = 0; i < 8; i++)
                #pragma unroll
                for (int j = 0; j < 8; j++)
                    acc[i][j] += av[i] * bv[j];
        }
        __syncthreads();
    }

    float4 bb0 = *(const float4*)(bias + n0 + tx*4);
    float4 bb1 = *(const float4*)(bias + n0 + 64 + tx*4);
    #pragma unroll
    for (int i = 0; i < 8; i++) {
        int m = m0 + ((i < 4) ? (ty*4 + i) : (64 + ty*4 + i - 4));
        float4 r0 = make_float4(acc[i][0]+bb0.x, acc[i][1]+bb0.y, acc[i][2]+bb0.z, acc[i][3]+bb0.w);
        float4 r1 = make_float4(acc[i][4]+bb1.x, acc[i][5]+bb1.y, acc[i][6]+bb1.z, acc[i][7]+bb1.w);
        if (LAYOUT == 0) {
            *(float4*)(out + (size_t)m * E_ + n0 + tx*4)      = r0;
            *(float4*)(out + (size_t)m * E_ + n0 + 64 + tx*4) = r1;
        } else {
            int b = m >> 11, l = m & (L_-1);
            int c0 = n0 + tx*4, c1 = n0 + 64 + tx*4;
            *(float4*)(out + (((size_t)(b*H_ + (c0>>6)) * L_) + l) * D_ + (c0 & 63)) = r0;
            *(float4*)(out + (((size_t)(b*H_ + (c1>>6)) * L_) + l) * D_ + (c1 & 63)) = r1;
        }
    }
}

// ---------------------------------------------------------------------------
// Attention via raw mma.sync m16n8k16 fp16 (fp32 accum), two passes over K.
// Block: 256 thr (8 warps), 128 q-rows; K processed in 32 tiles of 64 keys.
// Warp w owns q rows 16w..16w+15 for S, exp, attn store, PV, and ctx.
// Pass A: S -> exp*mask -> row sums. Pass B: recompute S, write normalized
// attn once, pack P from accum regs (layout-exact, no shuffle), ctx += P V.
// ---------------------------------------------------------------------------
__global__ __launch_bounds__(256, 2) void attn_mma(float* __restrict__ attn)
{
    const int tid = threadIdx.x, w = tid >> 5, lane = tid & 31;
    const int g = lane >> 2, t = lane & 3;
    const int bh = blockIdx.x, b = bh >> 3, h = bh & 7;
    const int q0 = blockIdx.y * 128;
    const int m0 = 16 * w;

    __shared__ __half Qs[128*LDH];
    __shared__ __half Ks[64*LDH];
    __shared__ __half Vs[64*LDH];
    __shared__ float s_inv[128];

    const float* Qb = g_QH + (size_t)bh * (L_*D_) + (size_t)q0 * D_;
    const float* Kb = g_KH + (size_t)bh * (L_*D_);
    const float* Vb = g_VH + (size_t)bh * (L_*D_);

    // Fill Q (fp32 -> fp16)
    #pragma unroll
    for (int it = 0; it < 8; it++) {
        int idx = tid + it*256;
        int row = idx >> 4, c4 = (idx & 15) * 4;
        float4 f = *(const float4*)(Qb + (size_t)row * D_ + c4);
        *(__half2*)&Qs[row*LDH + c4]     = __floats2half2_rn(f.x, f.y);
        *(__half2*)&Qs[row*LDH + c4 + 2] = __floats2half2_rn(f.z, f.w);
    }
    __syncthreads();

    // Hoisted Q A-fragments: 4 k16 blocks over d=64
    uint32_t qf[4][4];
    {
        uint32_t base = smem_u32(Qs);
        int rr = m0 + (lane & 7) + ((lane & 8) ? 8 : 0);
        int cc = (lane & 16) ? 8 : 0;
        #pragma unroll
        for (int j = 0; j < 4; j++)
            ldsm_x4(qf[j][0], qf[j][1], qf[j][2], qf[j][3],
                    base + (uint32_t)(rr*LDH + 16*j + cc) * 2);
    }

    const size_t mrow_lo = ((size_t)b*L_ + q0 + m0 + g) * L_;
    const size_t mrow_hi = mrow_lo + (size_t)8*L_;
    float* arow_lo = attn + ((size_t)(h*B_ + b)*L_ + q0 + m0 + g) * L_;
    float* arow_hi = arow_lo + (size_t)8*L_;

    const uint32_t ksb = smem_u32(Ks);
    const uint32_t vsb = smem_u32(Vs);
    const int krr = (lane & 7) + ((lane & 16) ? 8 : 0);  // B-frag n-row
    const int kcc = (lane & 8) ? 8 : 0;                  // B-frag k-col sel
    const int vrr = lane & 15;                           // V trans k-row
    const int vcc = (lane & 16) ? 8 : 0;                 // V trans d-col sel

    #define FILL_K(kt) do { \
        const float* Kt_ = Kb + (size_t)(kt)*64*D_; \
        _Pragma("unroll") \
        for (int it = 0; it < 4; it++) { \
            int idx = tid + it*256; \
            int row = idx >> 4, c4 = (idx & 15) * 4; \
            float4 f = *(const float4*)(Kt_ + (size_t)row * D_ + c4); \
            *(__half2*)&Ks[row*LDH + c4]     = __floats2half2_rn(f.x, f.y); \
            *(__half2*)&Ks[row*LDH + c4 + 2] = __floats2half2_rn(f.z, f.w); \
        } } while (0)

    #define FILL_V(kt) do { \
        const float* Vt_ = Vb + (size_t)(kt)*64*D_; \
        _Pragma("unroll") \
        for (int it = 0; it < 4; it++) { \
            int idx = tid + it*256; \
            int row = idx >> 4, c4 = (idx & 15) * 4; \
            float4 f = *(const float4*)(Vt_ + (size_t)row * D_ + c4); \
            *(__half2*)&Vs[row*LDH + c4]     = __floats2half2_rn(f.x, f.y); \
            *(__half2*)&Vs[row*LDH + c4 + 2] = __floats2half2_rn(f.z, f.w); \
        } } while (0)

    #define COMPUTE_S(S) do { \
        _Pragma("unroll") \
        for (int p = 0; p < 4; p++) { \
            uint32_t kf[4][4]; \
            _Pragma("unroll") \
            for (int j = 0; j < 4; j++) \
                ldsm_x4(kf[j][0], kf[j][1], kf[j][2], kf[j][3], \
                        ksb + (uint32_t)((16*p + krr)*LDH + 16*j + kcc) * 2); \
            _Pragma("unroll") \
            for (int j = 0; j < 4; j++) { \
                mma_f16(S[2*p],   qf[j], kf[j][0], kf[j][1]); \
                mma_f16(S[2*p+1], qf[j], kf[j][2], kf[j][3]); \
            } \
        } } while (0)

    // ---------------- Pass A: row sums ----------------
    float rs_lo = 0.f, rs_hi = 0.f;
    for (int kt = 0; kt < 32; kt++) {
        FILL_K(kt);
        __syncthreads();
        float S[8][4] = {};
        COMPUTE_S(S);
        __syncthreads();
        int colb = kt*64 + 2*t;
        #pragma unroll
        for (int n = 0; n < 8; n++) {
            int col = colb + n*8;
            __half2 mlo = *(const __half2*)&g_maskh[mrow_lo + col];
            __half2 mhi = *(const __half2*)&g_maskh[mrow_hi + col];
            rs_lo += exp2f(S[n][0]*EC) * __low2float(mlo) + exp2f(S[n][1]*EC) * __high2float(mlo);
            rs_hi += exp2f(S[n][2]*EC) * __low2float(mhi) + exp2f(S[n][3]*EC) * __high2float(mhi);
        }
    }
    rs_lo += __shfl_xor_sync(0xffffffffu, rs_lo, 1);
    rs_lo += __shfl_xor_sync(0xffffffffu, rs_lo, 2);
    rs_hi += __shfl_xor_sync(0xffffffffu, rs_hi, 1);
    rs_hi += __shfl_xor_sync(0xffffffffu, rs_hi, 2);
    if (t == 0) { s_inv[m0+g] = 1.f/rs_lo; s_inv[m0+g+8] = 1.f/rs_hi; }
    __syncthreads();
    const float iv_lo = s_inv[m0+g], iv_hi = s_inv[m0+g+8];

    // ---------------- Pass B: attn write + PV ----------------
    float ctx[8][4] = {};
    for (int kt = 0; kt < 32; kt++) {
        FILL_K(kt);
        FILL_V(kt);
        __syncthreads();
        float S[8][4] = {};
        COMPUTE_S(S);

        uint32_t pf[4][4];
        int colb = kt*64 + 2*t;
        #pragma unroll
        for (int n = 0; n < 8; n++) {
            int col = colb + n*8;
            __half2 mlo = *(const __half2*)&g_maskh[mrow_lo + col];
            __half2 mhi = *(const __half2*)&g_maskh[mrow_hi + col];
            float e0 = exp2f(S[n][0]*EC) * __low2float(mlo)  * iv_lo;
            float e1 = exp2f(S[n][1]*EC) * __high2float(mlo) * iv_lo;
            float e2 = exp2f(S[n][2]*EC) * __low2float(mhi)  * iv_hi;
            float e3 = exp2f(S[n][3]*EC) * __high2float(mhi) * iv_hi;
            *(float2*)&arow_lo[col] = make_float2(e0, e1);
            *(float2*)&arow_hi[col] = make_float2(e2, e3);
            pf[n>>1][(n&1)*2 + 0] = h2_u32(__floats2half2_rn(e0, e1));
            pf[n>>1][(n&1)*2 + 1] = h2_u32(__floats2half2_rn(e2, e3));
        }

        #pragma unroll
        for (int j = 0; j < 4; j++) {
            #pragma unroll
            for (int p = 0; p < 4; p++) {
                uint32_t v0, v1, v2, v3;
                ldsm_x4t(v0, v1, v2, v3,
                         vsb + (uint32_t)((16*j + vrr)*LDH + 16*p + vcc) * 2);
                mma_f16(ctx[2*p],   pf[j], v0, v1);
                mma_f16(ctx[2*p+1], pf[j], v2, v3);
            }
        }
        __syncthreads();
    }

    // ctx epilogue (P already normalized)
    float* cp_lo = g_CTX + ((size_t)b*L_ + q0 + m0 + g) * E_ + h*64;
    float* cp_hi = cp_lo + (size_t)8*E_;
    #pragma unroll
    for (int nd = 0; nd < 8; nd++) {
        *(float2*)&cp_lo[nd*8 + 2*t] = make_float2(ctx[nd][0], ctx[nd][1]);
        *(float2*)&cp_hi[nd*8 + 2*t] = make_float2(ctx[nd][2], ctx[nd][3]);
    }
}

// ---------------------------------------------------------------------------
// Fused residual + LayerNorm over rows of 512.
// ---------------------------------------------------------------------------
__global__ __launch_bounds__(256) void ln_kernel(
    const float* __restrict__ resid, const float* __restrict__ gamma,
    const float* __restrict__ beta, float* __restrict__ out)
{
    const int row = blockIdx.x;
    const int t = threadIdx.x;
    const float* fc = g_FC + (size_t)row * E_;
    const float* rsd = resid + (size_t)row * E_;

    float x0 = fc[t]       + rsd[t];
    float x1 = fc[t + 256] + rsd[t + 256];
    float s = x0 + x1, sq = x0*x0 + x1*x1;
    #pragma unroll
    for (int o = 16; o > 0; o >>= 1) {
        s  += __shfl_xor_sync(0xffffffffu, s,  o);
        sq += __shfl_xor_sync(0xffffffffu, sq, o);
    }
    __shared__ float ws[8], wq[8];
    __shared__ float s_mu, s_rstd;
    if ((t & 31) == 0) { ws[t >> 5] = s; wq[t >> 5] = sq; }
    __syncthreads();
    if (t == 0) {
        float S = 0.f, Q = 0.f;
        #pragma unroll
        for (int i = 0; i < 8; i++) { S += ws[i]; Q += wq[i]; }
        float mu = S * (1.f / E_);
        float var = Q * (1.f / E_) - mu * mu;
        s_mu = mu; s_rstd = rsqrtf(var + 1e-5f);
    }
    __syncthreads();
    float mu = s_mu, rstd = s_rstd;
    out[(size_t)row * E_ + t]       = (x0 - mu) * rstd * gamma[t]       + beta[t];
    out[(size_t)row * E_ + t + 256] = (x1 - mu) * rstd * gamma[t + 256] + beta[t + 256];
}

// ---------------------------------------------------------------------------
extern "C" void kernel_launch(void* const* d_in, const int* in_sizes, int n_in,
                              void* d_out, int out_size)
{
    const float* q    = (const float*)d_in[0];
    const float* k    = (const float*)d_in[1];
    const float* v    = (const float*)d_in[2];
    const void*  mask = d_in[3];
    const float* Wq   = (const float*)d_in[4];
    const float* bq   = (const float*)d_in[5];
    const float* Wk   = (const float*)d_in[6];
    const float* bk   = (const float*)d_in[7];
    const float* Wv   = (const float*)d_in[8];
    const float* bv   = (const float*)d_in[9];
    const float* Wfc  = (const float*)d_in[10];
    const float* bfc  = (const float*)d_in[11];
    const float* gamma= (const float*)d_in[12];
    const float* beta = (const float*)d_in[13];

    float* out  = (float*)d_out;
    float* attn = out + (size_t)M_ * E_;

    // Launch order puts attn at position 6 so ncu (-s 5 -c 1) captures it.
    dim3 gproj(M_/128, E_/128);                  // (64, 4)
    gemm_bias<1><<<gproj, 256>>>(q, Wq, bq, 0);  // 1
    gemm_bias<1><<<gproj, 256>>>(k, Wk, bk, 1);  // 2
    gemm_bias<1><<<gproj, 256>>>(v, Wv, bv, 2);  // 3

    probe_mask<<<(MASK_ELEMS/4)/256, 256>>>((const unsigned int*)mask);  // 4
    convert_mask<<<MASK_ELEMS/256, 256>>>(mask);                         // 5

    dim3 gattn(B_*H_, L_/128);                   // (32, 16): bh fastest for L2 mask reuse
    attn_mma<<<gattn, 256>>>(attn);              // 6  <-- profiled

    gemm_bias<0><<<gproj, 256>>>(nullptr, Wfc, bfc, 3);  // 7

    ln_kernel<<<M_, 256>>>(q, gamma, beta, out); // 8
}